// round 7
// baseline (speedup 1.0000x reference)
#include <cuda_runtime.h>
#include <cuda_fp16.h>

#define PHp 7
#define PWp 7
#define SRs 2
#define SCALEc 0.0625f
#define Bc 2
#define Cc 256
#define Hc 100
#define Wc 152
#define Rc 1024
#define HWc (Hc * Wc)          // 15200

// NHWC fp16 scratch: [B][H*W][C] halfs = 15.6 MB
__device__ __half g_nhwc[(size_t)Bc * HWc * Cc];

// ---------------- Phase 1: NCHW fp32 -> NHWC fp16 ----------------
__global__ void __launch_bounds__(256) transpose_kernel(const float* __restrict__ in)
{
    __shared__ float tile[64][33];
    int s0 = blockIdx.x * 32;           // HW tile (475 exact)
    int c0 = blockIdx.y * 64;           // C tile (4 exact)
    int b  = blockIdx.z;

    const float* ib = in + (size_t)b * Cc * HWc;
    __half* ob = g_nhwc + (size_t)b * HWc * Cc;

    int s = s0 + threadIdx.x;
    #pragma unroll
    for (int j = threadIdx.y; j < 64; j += 8)
        tile[j][threadIdx.x] = ib[(size_t)(c0 + j) * HWc + s];
    __syncthreads();

    int tx = threadIdx.x;
    #pragma unroll
    for (int j = threadIdx.y; j < 32; j += 8) {
        __half2 v = __floats2half2_rn(tile[2 * tx][j], tile[2 * tx + 1][j]);
        *(__half2*)(ob + (size_t)(s0 + j) * Cc + c0 + 2 * tx) = v;
    }
}

// ---------------- Phase 2: RoIAlign on NHWC fp16 ----------------
// One block per (roi, channel-half). 256 threads:
//   c8 = tid & 15  -> lane's 8-channel group (LDG.128 = 8 fp16 channels)
//   bs = tid >> 4  -> 16 parallel bin streams over 49 bins
// CPAD = 130: bin stride ≡ 2 (mod 32 banks) -> copy-out reads only 2-way
// conflicted (was 8-way at 132). Staging writes are 8B-aligned float2 STS.64.
#define CPAD 130
#define NSS  (PHp * PWp * SRs * SRs)    // 196 subsample records

__global__ void __launch_bounds__(256) roialign_nhwc_kernel(
    const float* __restrict__ rois,
    float* __restrict__ out)
{
    __shared__ float s[PHp * PWp * CPAD];   // 49*130*4 = 25,480 B
    __shared__ int4  ridx[NSS];             // 4 byte-offsets per subsample
    __shared__ uint4 rwgt[NSS];             // 4 duplicated-half2 weights

    int r    = blockIdx.x >> 1;
    int half = blockIdx.x & 1;
    int tid  = threadIdx.x;
    int c8   = tid & 15;
    int bs   = tid >> 4;

    const float* roi = rois + r * 5;
    int   b   = (int)roi[0];

    // ---- precompute: one subsample record per thread (tid < 196) ----
    if (tid < NSS) {
        float rsw = roi[1] * SCALEc;
        float rsh = roi[2] * SCALEc;
        float roi_w = fmaxf(roi[3] * SCALEc - rsw, 1.0f);
        float roi_h = fmaxf(roi[4] * SCALEc - rsh, 1.0f);
        float bin_h = roi_h * (1.0f / PHp);
        float bin_w = roi_w * (1.0f / PWp);

        int bin = tid >> 2;
        int ss  = tid & 3;
        int ph = bin / PWp, pw = bin - ph * PWp;
        int iy = ss >> 1,  ix = ss & 1;

        float y = rsh + ((float)ph + ((float)iy + 0.5f) * 0.5f) * bin_h;
        float x = rsw + ((float)pw + ((float)ix + 0.5f) * 0.5f) * bin_w;

        bool valid = (y >= -1.0f) && (y <= (float)Hc) &&
                     (x >= -1.0f) && (x <= (float)Wc);

        float yc = fminf(fmaxf(y, 0.0f), (float)(Hc - 1));
        float xc = fminf(fmaxf(x, 0.0f), (float)(Wc - 1));
        int ylo = (int)floorf(yc);
        int xlo = (int)floorf(xc);
        int yhi = min(ylo + 1, Hc - 1);
        int xhi = min(xlo + 1, Wc - 1);
        float ly = yc - (float)ylo;
        float lx = xc - (float)xlo;
        float hy = 1.0f - ly, hx = 1.0f - lx;

        float sc = valid ? 0.25f : 0.0f;           // fold subsample avg + validity
        float w11 = hy * hx * sc, w12 = hy * lx * sc;
        float w21 = ly * hx * sc, w22 = ly * lx * sc;

        // byte offsets into NHWC (row stride Cc*2 = 512 B)
        ridx[tid] = make_int4((ylo * Wc + xlo) * (Cc * 2),
                              (ylo * Wc + xhi) * (Cc * 2),
                              (yhi * Wc + xlo) * (Cc * 2),
                              (yhi * Wc + xhi) * (Cc * 2));
        __half2 h11 = __floats2half2_rn(w11, w11);
        __half2 h12 = __floats2half2_rn(w12, w12);
        __half2 h21 = __floats2half2_rn(w21, w21);
        __half2 h22 = __floats2half2_rn(w22, w22);
        rwgt[tid] = make_uint4(*(unsigned*)&h11, *(unsigned*)&h12,
                               *(unsigned*)&h21, *(unsigned*)&h22);
    }
    __syncthreads();

    const char* fbb = (const char*)(g_nhwc + (size_t)b * HWc * Cc
                                    + (half * 128 + c8 * 8));

    for (int bin = bs; bin < PHp * PWp; bin += 16) {
        float a0=0.f,a1=0.f,a2=0.f,a3=0.f,a4=0.f,a5=0.f,a6=0.f,a7=0.f;

        #pragma unroll
        for (int ss = 0; ss < 4; ss++) {
            int4  id = ridx[bin * 4 + ss];
            uint4 wv = rwgt[bin * 4 + ss];

            uint4 u11 = *(const uint4*)(fbb + id.x);
            uint4 u12 = *(const uint4*)(fbb + id.y);
            uint4 u21 = *(const uint4*)(fbb + id.z);
            uint4 u22 = *(const uint4*)(fbb + id.w);

            __half2 w11 = *(__half2*)&wv.x;
            __half2 w12 = *(__half2*)&wv.y;
            __half2 w21 = *(__half2*)&wv.z;
            __half2 w22 = *(__half2*)&wv.w;

            const __half2* c11 = (const __half2*)&u11;
            const __half2* c12 = (const __half2*)&u12;
            const __half2* c21 = (const __half2*)&u21;
            const __half2* c22 = (const __half2*)&u22;

            float2 f;
            #define SUB(J, AA, AB) { \
                __half2 sub = __hfma2(w11, c11[J], __hfma2(w12, c12[J], \
                              __hfma2(w21, c21[J], __hmul2(w22, c22[J])))); \
                f = __half22float2(sub); AA += f.x; AB += f.y; }
            SUB(0, a0, a1)
            SUB(1, a2, a3)
            SUB(2, a4, a5)
            SUB(3, a6, a7)
            #undef SUB
        }

        float* sp = s + bin * CPAD + c8 * 8;      // 8B-aligned (even word index)
        *(float2*)(sp)     = make_float2(a0, a1);
        *(float2*)(sp + 2) = make_float2(a2, a3);
        *(float2*)(sp + 4) = make_float2(a4, a5);
        *(float2*)(sp + 6) = make_float2(a6, a7);
    }
    __syncthreads();

    // Coalesced copy-out: out[r][c][ph][pw]; this block's 128*49 floats contiguous.
    float* ob = out + (size_t)r * (Cc * PHp * PWp) + (size_t)half * 128 * PHp * PWp;
    #pragma unroll 4
    for (int i = tid; i < 128 * PHp * PWp; i += 256) {
        int c = i / (PHp * PWp);
        int bin = i - c * (PHp * PWp);
        ob[i] = s[bin * CPAD + c];
    }
}

extern "C" void kernel_launch(void* const* d_in, const int* in_sizes, int n_in,
                              void* d_out, int out_size)
{
    const float* feat = (const float*)d_in[0];
    const float* rois = (const float*)d_in[1];
    float* out = (float*)d_out;

    dim3 tg(HWc / 32, Cc / 64, Bc);        // 475 x 4 x 2
    dim3 tb(32, 8, 1);
    transpose_kernel<<<tg, tb>>>(feat);

    roialign_nhwc_kernel<<<Rc * 2, 256>>>(rois, out);
}

// round 8
// speedup vs baseline: 1.2480x; 1.2480x over previous
#include <cuda_runtime.h>
#include <cuda_fp16.h>

#define PHp 7
#define PWp 7
#define SRs 2
#define SCALEc 0.0625f
#define Bc 2
#define Cc 256
#define Hc 100
#define Wc 152
#define Rc 1024
#define HWc (Hc * Wc)          // 15200

// NHWC fp16 scratch: [B][H*W][C] halfs = 15.6 MB
__device__ __half g_nhwc[(size_t)Bc * HWc * Cc];

// ---------------- Phase 1: NCHW fp32 -> NHWC fp16 ----------------
__global__ void __launch_bounds__(256) transpose_kernel(const float* __restrict__ in)
{
    __shared__ float tile[64][33];
    int s0 = blockIdx.x * 32;           // HW tile (475 exact)
    int c0 = blockIdx.y * 64;           // C tile (4 exact)
    int b  = blockIdx.z;

    const float* ib = in + (size_t)b * Cc * HWc;
    __half* ob = g_nhwc + (size_t)b * HWc * Cc;

    int s = s0 + threadIdx.x;
    int tid = threadIdx.y * 32 + threadIdx.x;
    #pragma unroll
    for (int j = threadIdx.y; j < 64; j += 8)
        tile[j][threadIdx.x] = ib[(size_t)(c0 + j) * HWc + s];
    __syncthreads();

    // Write side: each thread packs 8 consecutive channels -> uint4 STG.128.
    int g  = tid & 7;          // channel group of 8 within the 64-ch tile
    int sL = tid >> 3;         // 0..31 spatial
    __half2 h2[4];
    #pragma unroll
    for (int k = 0; k < 4; k++)
        h2[k] = __floats2half2_rn(tile[g * 8 + 2 * k][sL], tile[g * 8 + 2 * k + 1][sL]);
    uint4 v = make_uint4(*(unsigned*)&h2[0], *(unsigned*)&h2[1],
                         *(unsigned*)&h2[2], *(unsigned*)&h2[3]);
    *(uint4*)(ob + (size_t)(s0 + sL) * Cc + c0 + g * 8) = v;
}

// ---------------- Phase 2: RoIAlign on NHWC fp16 ----------------
// One block per (roi, channel-half). 256 threads:
//   c8 = tid & 15  -> lane's 8-channel group (LDG.128 = 8 fp16 channels)
//   bs = tid >> 4  -> 16 parallel bin streams over 49 bins
// Output staged in fp16, flat [c_local*49 + bin]: STS.16 writes (2-way max),
// copy-out is perfectly contiguous uint reads + float2 coalesced stores.
#define NSS  (PHp * PWp * SRs * SRs)    // 196 subsample records
#define NOUT (128 * PHp * PWp)          // 6272 outputs per block

__global__ void __launch_bounds__(256) roialign_nhwc_kernel(
    const float* __restrict__ rois,
    float* __restrict__ out)
{
    __shared__ __align__(16) __half s_h[NOUT];   // 12,544 B
    __shared__ int4  ridx[NSS];                  // 4 byte-offsets per subsample
    __shared__ uint4 rwgt[NSS];                  // 4 duplicated-half2 weights

    int r    = blockIdx.x >> 1;
    int half = blockIdx.x & 1;
    int tid  = threadIdx.x;
    int c8   = tid & 15;
    int bs   = tid >> 4;

    const float* roi = rois + r * 5;
    int   b   = (int)roi[0];

    // ---- precompute: one subsample record per thread (tid < 196) ----
    if (tid < NSS) {
        float rsw = roi[1] * SCALEc;
        float rsh = roi[2] * SCALEc;
        float roi_w = fmaxf(roi[3] * SCALEc - rsw, 1.0f);
        float roi_h = fmaxf(roi[4] * SCALEc - rsh, 1.0f);
        float bin_h = roi_h * (1.0f / PHp);
        float bin_w = roi_w * (1.0f / PWp);

        int bin = tid >> 2;
        int ss  = tid & 3;
        int ph = bin / PWp, pw = bin - ph * PWp;
        int iy = ss >> 1,  ix = ss & 1;

        float y = rsh + ((float)ph + ((float)iy + 0.5f) * 0.5f) * bin_h;
        float x = rsw + ((float)pw + ((float)ix + 0.5f) * 0.5f) * bin_w;

        bool valid = (y >= -1.0f) && (y <= (float)Hc) &&
                     (x >= -1.0f) && (x <= (float)Wc);

        float yc = fminf(fmaxf(y, 0.0f), (float)(Hc - 1));
        float xc = fminf(fmaxf(x, 0.0f), (float)(Wc - 1));
        int ylo = (int)floorf(yc);
        int xlo = (int)floorf(xc);
        int yhi = min(ylo + 1, Hc - 1);
        int xhi = min(xlo + 1, Wc - 1);
        float ly = yc - (float)ylo;
        float lx = xc - (float)xlo;
        float hy = 1.0f - ly, hx = 1.0f - lx;

        float sc = valid ? 0.25f : 0.0f;           // fold subsample avg + validity
        float w11 = hy * hx * sc, w12 = hy * lx * sc;
        float w21 = ly * hx * sc, w22 = ly * lx * sc;

        // byte offsets into NHWC (row stride Cc*2 = 512 B)
        ridx[tid] = make_int4((ylo * Wc + xlo) * (Cc * 2),
                              (ylo * Wc + xhi) * (Cc * 2),
                              (yhi * Wc + xlo) * (Cc * 2),
                              (yhi * Wc + xhi) * (Cc * 2));
        __half2 h11 = __floats2half2_rn(w11, w11);
        __half2 h12 = __floats2half2_rn(w12, w12);
        __half2 h21 = __floats2half2_rn(w21, w21);
        __half2 h22 = __floats2half2_rn(w22, w22);
        rwgt[tid] = make_uint4(*(unsigned*)&h11, *(unsigned*)&h12,
                               *(unsigned*)&h21, *(unsigned*)&h22);
    }
    __syncthreads();

    const char* fbb = (const char*)(g_nhwc + (size_t)b * HWc * Cc
                                    + (half * 128 + c8 * 8));

    for (int bin = bs; bin < PHp * PWp; bin += 16) {
        float a0=0.f,a1=0.f,a2=0.f,a3=0.f,a4=0.f,a5=0.f,a6=0.f,a7=0.f;

        #pragma unroll
        for (int ss = 0; ss < 4; ss++) {
            int4  id = ridx[bin * 4 + ss];
            uint4 wv = rwgt[bin * 4 + ss];

            uint4 u11 = *(const uint4*)(fbb + id.x);
            uint4 u12 = *(const uint4*)(fbb + id.y);
            uint4 u21 = *(const uint4*)(fbb + id.z);
            uint4 u22 = *(const uint4*)(fbb + id.w);

            __half2 w11 = *(__half2*)&wv.x;
            __half2 w12 = *(__half2*)&wv.y;
            __half2 w21 = *(__half2*)&wv.z;
            __half2 w22 = *(__half2*)&wv.w;

            const __half2* c11 = (const __half2*)&u11;
            const __half2* c12 = (const __half2*)&u12;
            const __half2* c21 = (const __half2*)&u21;
            const __half2* c22 = (const __half2*)&u22;

            float2 f;
            #define SUB(J, AA, AB) { \
                __half2 sub = __hfma2(w11, c11[J], __hfma2(w12, c12[J], \
                              __hfma2(w21, c21[J], __hmul2(w22, c22[J])))); \
                f = __half22float2(sub); AA += f.x; AB += f.y; }
            SUB(0, a0, a1)
            SUB(1, a2, a3)
            SUB(2, a4, a5)
            SUB(3, a6, a7)
            #undef SUB
        }

        // fp16 staging at [c_local*49 + bin], c_local = c8*8 + j
        __half* hp = s_h + (c8 * 8) * (PHp * PWp) + bin;
        hp[0 * 49] = __float2half_rn(a0);
        hp[1 * 49] = __float2half_rn(a1);
        hp[2 * 49] = __float2half_rn(a2);
        hp[3 * 49] = __float2half_rn(a3);
        hp[4 * 49] = __float2half_rn(a4);
        hp[5 * 49] = __float2half_rn(a5);
        hp[6 * 49] = __float2half_rn(a6);
        hp[7 * 49] = __float2half_rn(a7);
    }
    __syncthreads();

    // Copy-out: staging is already in output order -> contiguous uint reads,
    // convert to fp32, coalesced float2 stores.
    float* ob = out + (size_t)r * (Cc * PHp * PWp) + (size_t)half * NOUT;
    const unsigned* sw = (const unsigned*)s_h;
    #pragma unroll 4
    for (int t = tid; t < NOUT / 2; t += 256) {
        unsigned u = sw[t];
        float2 f = __half22float2(*(__half2*)&u);
        *(float2*)(ob + 2 * t) = f;
    }
}

extern "C" void kernel_launch(void* const* d_in, const int* in_sizes, int n_in,
                              void* d_out, int out_size)
{
    const float* feat = (const float*)d_in[0];
    const float* rois = (const float*)d_in[1];
    float* out = (float*)d_out;

    dim3 tg(HWc / 32, Cc / 64, Bc);        // 475 x 4 x 2
    dim3 tb(32, 8, 1);
    transpose_kernel<<<tg, tb>>>(feat);

    roialign_nhwc_kernel<<<Rc * 2, 256>>>(rois, out);
}

// round 11
// speedup vs baseline: 1.5167x; 1.2153x over previous
#include <cuda_runtime.h>
#include <cuda_fp16.h>

#define PHp 7
#define PWp 7
#define SRs 2
#define SCALEc 0.0625f
#define Bc 2
#define Cc 256
#define Hc 100
#define Wc 152
#define Rc 1024
#define HWc (Hc * Wc)          // 15200 = 95 * 160

// NHWC fp16 scratch: [B][H*W][C] halfs = 15.6 MB
__device__ __align__(16) __half g_nhwc[(size_t)Bc * HWc * Cc];

// ---------------- Phase 1: NCHW fp32 -> NHWC fp16 (bandwidth-optimized) ----
// Tile: 64 channels x 160 spatial. 256 threads.
// Load: 10x LDG.128 per thread back-to-back (MLP~10, hides DRAM latency).
// Smem: fp16 tile [64][170]; stores are 4B uints (always aligned),
//       read stride 8*170 halfs = 680 words ≡ 8 (mod 32) -> 2-way max.
// Write: 8-channel uint4 assembled from half2 -> coalesced STG.128.
#define TSP 160
#define TPAD 170

__global__ void __launch_bounds__(256) transpose_kernel(const float* __restrict__ in)
{
    __shared__ __half t[64 * TPAD];     // 21,760 B

    int s0 = blockIdx.x * TSP;          // 95 tiles exact
    int c0 = blockIdx.y * 64;           // 4 tiles exact
    int b  = blockIdx.z;
    int tid = threadIdx.x;

    const float* ib = in + ((size_t)b * Cc + c0) * HWc + s0;
    __half* ob = g_nhwc + (size_t)b * HWc * Cc + c0;

    // ---- load: 64 rows x 40 float4 ----
    #pragma unroll
    for (int p = 0; p < 10; p++) {
        int idx = p * 256 + tid;
        int j  = idx / 40;              // channel row 0..63
        int c4 = idx - j * 40;          // float4 col 0..39
        float4 v = *(const float4*)(ib + (size_t)j * HWc + c4 * 4);
        __half2 h0 = __floats2half2_rn(v.x, v.y);
        __half2 h1 = __floats2half2_rn(v.z, v.w);
        unsigned* w = (unsigned*)(t + j * TPAD + c4 * 4);   // 4B aligned always
        w[0] = *(unsigned*)&h0;
        w[1] = *(unsigned*)&h1;
    }
    __syncthreads();

    // ---- write: (s, g) -> uint4 of 8 channels, coalesced STG.128 ----
    int g = tid & 7;                    // 8-channel group
    const __half* tg8 = t + (g * 8) * TPAD;
    #pragma unroll
    for (int p = 0; p < 5; p++) {
        int s = p * 32 + (tid >> 3);    // spatial 0..159
        __half2 p0 = __halves2half2(tg8[0 * TPAD + s], tg8[1 * TPAD + s]);
        __half2 p1 = __halves2half2(tg8[2 * TPAD + s], tg8[3 * TPAD + s]);
        __half2 p2 = __halves2half2(tg8[4 * TPAD + s], tg8[5 * TPAD + s]);
        __half2 p3 = __halves2half2(tg8[6 * TPAD + s], tg8[7 * TPAD + s]);
        uint4 v = make_uint4(*(unsigned*)&p0, *(unsigned*)&p1,
                             *(unsigned*)&p2, *(unsigned*)&p3);
        *(uint4*)(ob + (size_t)(s0 + s) * Cc + g * 8) = v;
    }
}

// ---------------- Phase 2: RoIAlign on NHWC fp16 (unchanged from R8) -------
#define NSS  (PHp * PWp * SRs * SRs)    // 196 subsample records
#define NOUT (128 * PHp * PWp)          // 6272 outputs per block

__global__ void __launch_bounds__(256) roialign_nhwc_kernel(
    const float* __restrict__ rois,
    float* __restrict__ out)
{
    __shared__ __align__(16) __half s_h[NOUT];   // 12,544 B
    __shared__ int4  ridx[NSS];
    __shared__ uint4 rwgt[NSS];

    int r    = blockIdx.x >> 1;
    int half = blockIdx.x & 1;
    int tid  = threadIdx.x;
    int c8   = tid & 15;
    int bs   = tid >> 4;

    const float* roi = rois + r * 5;
    int   b   = (int)roi[0];

    if (tid < NSS) {
        float rsw = roi[1] * SCALEc;
        float rsh = roi[2] * SCALEc;
        float roi_w = fmaxf(roi[3] * SCALEc - rsw, 1.0f);
        float roi_h = fmaxf(roi[4] * SCALEc - rsh, 1.0f);
        float bin_h = roi_h * (1.0f / PHp);
        float bin_w = roi_w * (1.0f / PWp);

        int bin = tid >> 2;
        int ss  = tid & 3;
        int ph = bin / PWp, pw = bin - ph * PWp;
        int iy = ss >> 1,  ix = ss & 1;

        float y = rsh + ((float)ph + ((float)iy + 0.5f) * 0.5f) * bin_h;
        float x = rsw + ((float)pw + ((float)ix + 0.5f) * 0.5f) * bin_w;

        bool valid = (y >= -1.0f) && (y <= (float)Hc) &&
                     (x >= -1.0f) && (x <= (float)Wc);

        float yc = fminf(fmaxf(y, 0.0f), (float)(Hc - 1));
        float xc = fminf(fmaxf(x, 0.0f), (float)(Wc - 1));
        int ylo = (int)floorf(yc);
        int xlo = (int)floorf(xc);
        int yhi = min(ylo + 1, Hc - 1);
        int xhi = min(xlo + 1, Wc - 1);
        float ly = yc - (float)ylo;
        float lx = xc - (float)xlo;
        float hy = 1.0f - ly, hx = 1.0f - lx;

        float sc = valid ? 0.25f : 0.0f;
        float w11 = hy * hx * sc, w12 = hy * lx * sc;
        float w21 = ly * hx * sc, w22 = ly * lx * sc;

        ridx[tid] = make_int4((ylo * Wc + xlo) * (Cc * 2),
                              (ylo * Wc + xhi) * (Cc * 2),
                              (yhi * Wc + xlo) * (Cc * 2),
                              (yhi * Wc + xhi) * (Cc * 2));
        __half2 h11 = __floats2half2_rn(w11, w11);
        __half2 h12 = __floats2half2_rn(w12, w12);
        __half2 h21 = __floats2half2_rn(w21, w21);
        __half2 h22 = __floats2half2_rn(w22, w22);
        rwgt[tid] = make_uint4(*(unsigned*)&h11, *(unsigned*)&h12,
                               *(unsigned*)&h21, *(unsigned*)&h22);
    }
    __syncthreads();

    const char* fbb = (const char*)(g_nhwc + (size_t)b * HWc * Cc
                                    + (half * 128 + c8 * 8));

    for (int bin = bs; bin < PHp * PWp; bin += 16) {
        float a0=0.f,a1=0.f,a2=0.f,a3=0.f,a4=0.f,a5=0.f,a6=0.f,a7=0.f;

        #pragma unroll
        for (int ss = 0; ss < 4; ss++) {
            int4  id = ridx[bin * 4 + ss];
            uint4 wv = rwgt[bin * 4 + ss];

            uint4 u11 = *(const uint4*)(fbb + id.x);
            uint4 u12 = *(const uint4*)(fbb + id.y);
            uint4 u21 = *(const uint4*)(fbb + id.z);
            uint4 u22 = *(const uint4*)(fbb + id.w);

            __half2 w11 = *(__half2*)&wv.x;
            __half2 w12 = *(__half2*)&wv.y;
            __half2 w21 = *(__half2*)&wv.z;
            __half2 w22 = *(__half2*)&wv.w;

            const __half2* c11 = (const __half2*)&u11;
            const __half2* c12 = (const __half2*)&u12;
            const __half2* c21 = (const __half2*)&u21;
            const __half2* c22 = (const __half2*)&u22;

            float2 f;
            #define SUB(J, AA, AB) { \
                __half2 sub = __hfma2(w11, c11[J], __hfma2(w12, c12[J], \
                              __hfma2(w21, c21[J], __hmul2(w22, c22[J])))); \
                f = __half22float2(sub); AA += f.x; AB += f.y; }
            SUB(0, a0, a1)
            SUB(1, a2, a3)
            SUB(2, a4, a5)
            SUB(3, a6, a7)
            #undef SUB
        }

        __half* hp = s_h + (c8 * 8) * (PHp * PWp) + bin;
        hp[0 * 49] = __float2half_rn(a0);
        hp[1 * 49] = __float2half_rn(a1);
        hp[2 * 49] = __float2half_rn(a2);
        hp[3 * 49] = __float2half_rn(a3);
        hp[4 * 49] = __float2half_rn(a4);
        hp[5 * 49] = __float2half_rn(a5);
        hp[6 * 49] = __float2half_rn(a6);
        hp[7 * 49] = __float2half_rn(a7);
    }
    __syncthreads();

    float* ob = out + (size_t)r * (Cc * PHp * PWp) + (size_t)half * NOUT;
    const unsigned* sw = (const unsigned*)s_h;
    #pragma unroll 4
    for (int t = tid; t < NOUT / 2; t += 256) {
        unsigned u = sw[t];
        float2 f = __half22float2(*(__half2*)&u);
        *(float2*)(ob + 2 * t) = f;
    }
}

extern "C" void kernel_launch(void* const* d_in, const int* in_sizes, int n_in,
                              void* d_out, int out_size)
{
    const float* feat = (const float*)d_in[0];
    const float* rois = (const float*)d_in[1];
    float* out = (float*)d_out;

    dim3 tg(HWc / TSP, Cc / 64, Bc);        // 95 x 4 x 2
    transpose_kernel<<<tg, 256>>>(feat);

    roialign_nhwc_kernel<<<Rc * 2, 256>>>(rois, out);
}